// round 11
// baseline (speedup 1.0000x reference)
#include <cuda_runtime.h>
#include <cuda_bf16.h>
#include <cfloat>

#define NN  50000
#define EE  1600000
#define FIN 8
#define HIDD 1000
#define RR  100
#define PACK24 16777216.0   // 2^24: g_sc = sum + cnt * 2^24 (exact unpack)

#define R8   8              // rows per GEMV0 block
#define CH   25             // column chunks per GEMV0 row
#define C4   500            // float4s per chunk (NN/4/CH)

// ---------------- scratch (no allocations allowed) ----------------
__device__ double                 g_sc[NN];          // packed (sum of p, count)
__device__ __align__(16) unsigned g_maxk[NN * FIN];  // encoded per-feature running max
__device__ __align__(16) unsigned g_key[NN * FIN];   // encoded X features per node
__device__ float g_x[NN];         // embedding (MLP input)
__device__ float g_h0pre[HIDD];   // GEMV0 pre-activation accumulator (seeded with b0)
__device__ float g_h1[HIDD];
__device__ int   g_idx64;         // 1 if edge_index is int64, 0 if int32

// ---------------- helpers ----------------
// Order-preserving float <-> uint32 encoding (monotone, exact round-trip).
__device__ __forceinline__ unsigned encf(float f) {
    unsigned u = __float_as_uint(f);
    return (u & 0x80000000u) ? ~u : (u | 0x80000000u);
}
__device__ __forceinline__ float decf(unsigned k) {
    unsigned u = (k & 0x80000000u) ? (k & 0x7fffffffu) : ~k;
    return __uint_as_float(u);
}
__device__ __forceinline__ float dot8(float4 a, float4 b, const float* __restrict__ w) {
    return a.x * w[0] + a.y * w[1] + a.z * w[2] + a.w * w[3]
         + b.x * w[4] + b.y * w[5] + b.z * w[6] + b.w * w[7];
}

// ---------------- kernels ----------------

// Per node: zero accumulators, encode keys from X; seed h0pre with b0.
// Thread 0 sniffs edge-index dtype: int32 data reinterpreted as int64 packs two
// random ids per word -> out-of-range values w.p. ~1 over 16 samples.
__global__ void init_kernel(const float* __restrict__ X,
                            const float* __restrict__ b0,
                            const long long* __restrict__ ei) {
    int i = blockIdx.x * blockDim.x + threadIdx.x;
    if (i == 0) {
        int ok = 1;
        #pragma unroll
        for (int k = 0; k < 16; k++) {
            long long v = ei[k];
            if (v < 0 || v >= (long long)NN) ok = 0;
        }
        g_idx64 = ok;
    }
    if (i < HIDD) g_h0pre[i] = b0[i];
    if (i >= NN) return;
    g_sc[i] = 0.0;
    // init max keys to 0: every real-data key is > 0; masked by cnt anyway
    uint4 z = make_uint4(0u, 0u, 0u, 0u);
    ((uint4*)&g_maxk[(size_t)i * FIN])[0] = z;
    ((uint4*)&g_maxk[(size_t)i * FIN])[1] = z;
    const float4* x4 = (const float4*)(X + (size_t)i * FIN);
    float4 a = x4[0], b = x4[1];
    uint4 k0 = make_uint4(encf(a.x), encf(a.y), encf(a.z), encf(a.w));
    uint4 k1 = make_uint4(encf(b.x), encf(b.y), encf(b.z), encf(b.w));
    ((uint4*)&g_key[(size_t)i * FIN])[0] = k0;
    ((uint4*)&g_key[(size_t)i * FIN])[1] = k1;
}

// Four edges per thread, ALL scattered loads batched up front (16 independent
// LDG.128 in flight per thread) before any dependent compute/atomics.
__global__ void __launch_bounds__(256) edge_kernel(const void* __restrict__ eiv,
                                                   const float* __restrict__ lin_l_w) {
    int t = blockIdx.x * blockDim.x + threadIdx.x;
    if (t * 4 >= EE) return;
    int s[4], d[4];
    if (g_idx64) {
        const longlong2* S = (const longlong2*)eiv;
        const longlong2* D = (const longlong2*)((const long long*)eiv + EE);
        longlong2 a = S[2 * t], b = S[2 * t + 1];
        longlong2 c = D[2 * t], e = D[2 * t + 1];
        s[0] = (int)a.x; s[1] = (int)a.y; s[2] = (int)b.x; s[3] = (int)b.y;
        d[0] = (int)c.x; d[1] = (int)c.y; d[2] = (int)e.x; d[3] = (int)e.y;
    } else {
        const int4* S = (const int4*)eiv;
        const int4* D = (const int4*)((const int*)eiv + EE);
        int4 a = S[t], c = D[t];
        s[0] = a.x; s[1] = a.y; s[2] = a.z; s[3] = a.w;
        d[0] = c.x; d[1] = c.y; d[2] = c.z; d[3] = c.w;
    }
    // batch phase: 8 key loads + 8 filter loads, all independent
    uint4 k0[4], k1[4], c0[4], c1[4];
    #pragma unroll
    for (int k = 0; k < 4; k++) {
        const uint4* kp = (const uint4*)&g_key[(size_t)s[k] * FIN];
        k0[k] = __ldg(kp);
        k1[k] = __ldg(kp + 1);
    }
    #pragma unroll
    for (int k = 0; k < 4; k++) {
        const uint4* mp = (const uint4*)&g_maxk[(size_t)d[k] * FIN];
        c0[k] = __ldg(mp);
        c1[k] = __ldg(mp + 1);
    }
    float4 wa = __ldg((const float4*)lin_l_w);
    float4 wb = __ldg((const float4*)lin_l_w + 1);
    // compute/RED phase
    #pragma unroll
    for (int k = 0; k < 4; k++) {
        // p = dot(X[s], lin_l_w), decoded exactly from the keys
        float p = decf(k0[k].x) * wa.x + decf(k0[k].y) * wa.y
                + decf(k0[k].z) * wa.z + decf(k0[k].w) * wa.w
                + decf(k1[k].x) * wb.x + decf(k1[k].y) * wb.y
                + decf(k1[k].z) * wb.z + decf(k1[k].w) * wb.w;
        atomicAdd(&g_sc[d[k]], (double)p + PACK24);  // mean path + count, one RED
        // max path: read-filtered atomicMax (monotone => stale reads are safe)
        unsigned* m = &g_maxk[(size_t)d[k] * FIN];
        if (k0[k].x > c0[k].x) atomicMax(m + 0, k0[k].x);
        if (k0[k].y > c0[k].y) atomicMax(m + 1, k0[k].y);
        if (k0[k].z > c0[k].z) atomicMax(m + 2, k0[k].z);
        if (k0[k].w > c0[k].w) atomicMax(m + 3, k0[k].w);
        if (k1[k].x > c1[k].x) atomicMax(m + 4, k1[k].x);
        if (k1[k].y > c1[k].y) atomicMax(m + 5, k1[k].y);
        if (k1[k].z > c1[k].z) atomicMax(m + 6, k1[k].z);
        if (k1[k].w > c1[k].w) atomicMax(m + 7, k1[k].w);
    }
}

__global__ void node_kernel(const float* __restrict__ X,
                            const float* __restrict__ lin_l_b,
                            const float* __restrict__ lin_r_w,
                            const float* __restrict__ lin_l1_w,
                            const float* __restrict__ lin_l1_b,
                            const float* __restrict__ lin_r1_w,
                            float* __restrict__ out) {
    int i = blockIdx.x * blockDim.x + threadIdx.x;
    if (i >= NN) return;
    double acc = g_sc[i];
    int cnt = __double2int_rn(acc * (1.0 / PACK24));
    float sum = (float)(acc - (double)cnt * PACK24);
    float mean = sum / fmaxf((float)cnt, 1.0f);       // agg_mean . lin_l_w
    float mx = 0.0f;
    if (cnt > 0) {
        const uint4* mk = (const uint4*)&g_maxk[(size_t)i * FIN];
        uint4 c0 = mk[0], c1 = mk[1];
        mx = decf(c0.x) * lin_l1_w[0] + decf(c0.y) * lin_l1_w[1]
           + decf(c0.z) * lin_l1_w[2] + decf(c0.w) * lin_l1_w[3]
           + decf(c1.x) * lin_l1_w[4] + decf(c1.y) * lin_l1_w[5]
           + decf(c1.z) * lin_l1_w[6] + decf(c1.w) * lin_l1_w[7];
    }
    const float4* x4 = (const float4*)(X + (size_t)i * FIN);
    float4 a = x4[0], b = x4[1];
    float hm = fmaxf(mean + lin_l_b[0]  + dot8(a, b, lin_r_w),  0.0f);
    float hx = fmaxf(mx   + lin_l1_b[0] + dot8(a, b, lin_r1_w), 0.0f);
    float v = hm + hx;
    out[i] = v;   // X_embedding slot of output
    g_x[i] = v;   // MLP input
}

// GEMV0 split: block = (8 rows, 1 of 25 column chunks). x slice loaded once,
// reused across 8 W rows (8x less L2 x-traffic). Per-warp partials go straight
// to g_h0pre (pre-seeded with b0) via atomicAdd — no inter-warp reduction.
__global__ void __launch_bounds__(256) gemv0_partial_kernel(const float* __restrict__ W0,
                                                            const float* __restrict__ x) {
    int rb    = blockIdx.x / CH;   // row group
    int chunk = blockIdx.x % CH;
    int row = rb * R8;
    const float4* x4 = (const float4*)x;
    const float4* w[R8];
    #pragma unroll
    for (int r = 0; r < R8; r++)
        w[r] = (const float4*)(W0 + (size_t)(row + r) * NN);
    float a[R8];
    #pragma unroll
    for (int r = 0; r < R8; r++) a[r] = 0.0f;
    int base = chunk * C4;
    for (int c = base + threadIdx.x; c < base + C4; c += 256) {
        float4 v = x4[c];
        #pragma unroll
        for (int r = 0; r < R8; r++) {
            float4 p = w[r][c];
            a[r] += p.x * v.x + p.y * v.y + p.z * v.z + p.w * v.w;
        }
    }
    #pragma unroll
    for (int r = 0; r < R8; r++) {
        #pragma unroll
        for (int o = 16; o; o >>= 1)
            a[r] += __shfl_down_sync(0xffffffffu, a[r], o);
    }
    if ((threadIdx.x & 31) == 0) {
        #pragma unroll
        for (int r = 0; r < R8; r++)
            atomicAdd(&g_h0pre[row + r], a[r]);
    }
}

// y[row] = relu(W[row,:] . act(x) + b[row]); act = relu if RELU_IN (fused from GEMV0).
template <int THREADS, int RELU_IN>
__global__ void gemv_relu_kernel(const float* __restrict__ W,
                                 const float* __restrict__ b,
                                 const float* __restrict__ x,
                                 float* __restrict__ y,
                                 int in4) {  // in_dim / 4
    int row = blockIdx.x;
    const float4* w4 = (const float4*)(W + (size_t)row * (size_t)in4 * 4);
    const float4* x4 = (const float4*)x;
    float acc = 0.0f;
    for (int c = threadIdx.x; c < in4; c += THREADS) {
        float4 w = w4[c];
        float4 v = x4[c];
        if (RELU_IN) {
            v.x = fmaxf(v.x, 0.f); v.y = fmaxf(v.y, 0.f);
            v.z = fmaxf(v.z, 0.f); v.w = fmaxf(v.w, 0.f);
        }
        acc += w.x * v.x + w.y * v.y + w.z * v.z + w.w * v.w;
    }
    __shared__ float sh[THREADS / 32];
    #pragma unroll
    for (int o = 16; o; o >>= 1) acc += __shfl_down_sync(0xffffffffu, acc, o);
    int lane = threadIdx.x & 31, wid = threadIdx.x >> 5;
    if (lane == 0) sh[wid] = acc;
    __syncthreads();
    if (wid == 0) {
        acc = (lane < THREADS / 32) ? sh[lane] : 0.0f;
        #pragma unroll
        for (int o = 16; o; o >>= 1) acc += __shfl_down_sync(0xffffffffu, acc, o);
        if (lane == 0) y[row] = fmaxf(acc + b[row], 0.0f);
    }
}

// ---------------- launch ----------------
extern "C" void kernel_launch(void* const* d_in, const int* in_sizes, int n_in,
                              void* d_out, int out_size) {
    const float* X        = (const float*)d_in[0];
    const void*  ei       = d_in[1];               // int64 or int32, detected on device
    const float* lin_l_w  = (const float*)d_in[2];
    const float* lin_l_b  = (const float*)d_in[3];
    const float* lin_r_w  = (const float*)d_in[4];
    const float* lin_l1_w = (const float*)d_in[5];
    const float* lin_l1_b = (const float*)d_in[6];
    const float* lin_r1_w = (const float*)d_in[7];
    const float* W0       = (const float*)d_in[8];
    const float* b0       = (const float*)d_in[9];
    const float* W1       = (const float*)d_in[10];
    const float* b1       = (const float*)d_in[11];
    const float* W2       = (const float*)d_in[12];
    const float* b2       = (const float*)d_in[13];
    float* out = (float*)d_out;  // [NN + RR] = embedding ++ mlp_out

    init_kernel<<<(NN + 255) / 256, 256>>>(X, b0, (const long long*)ei);
    edge_kernel<<<(EE / 4 + 255) / 256, 256>>>(ei, lin_l_w);
    node_kernel<<<(NN + 255) / 256, 256>>>(X, lin_l_b, lin_r_w,
                                           lin_l1_w, lin_l1_b, lin_r1_w, out);

    float* g_x_ptr;  float* g_h0pre_ptr;  float* g_h1_ptr;
    cudaGetSymbolAddress((void**)&g_x_ptr,     g_x);
    cudaGetSymbolAddress((void**)&g_h0pre_ptr, g_h0pre);
    cudaGetSymbolAddress((void**)&g_h1_ptr,    g_h1);

    gemv0_partial_kernel<<<(HIDD / R8) * CH, 256>>>(W0, g_x_ptr);              // 1000x50000
    gemv_relu_kernel<256, 1><<<HIDD, 256>>>(W1, b1, g_h0pre_ptr, g_h1_ptr, HIDD / 4);
    gemv_relu_kernel<256, 0><<<RR,   256>>>(W2, b2, g_h1_ptr, out + NN, HIDD / 4);
}

// round 12
// speedup vs baseline: 1.4088x; 1.4088x over previous
#include <cuda_runtime.h>
#include <cuda_bf16.h>
#include <cfloat>

#define NN  50000
#define EE  1600000
#define FIN 8
#define HIDD 1000
#define RR  100
#define PACK24 16777216.0   // 2^24: g_sc = sum + cnt * 2^24 (exact unpack)

#define R4   4              // rows per GEMV0 block (proven best)
#define CH   10             // column chunks per GEMV0 row
#define C4   1250           // float4s per chunk (NN/4/CH)
#define PF_ROW 600          // W0 rows [PF_ROW, HIDD) prefetched into L2

#define EDGE_BLOCKS 3125    // 3125*256 threads; 8 warps/blk * 64 edges/warp = EE exactly

// ---------------- scratch (no allocations allowed) ----------------
__device__ double                 g_sc[NN];          // packed (sum of p, count)
__device__ __align__(16) unsigned g_maxk[NN * FIN];  // encoded per-feature running max
__device__ __align__(16) unsigned g_key[NN * FIN];   // encoded X features per node
__device__ float g_x[NN];         // embedding (MLP input)
__device__ float g_h0pre[HIDD];   // GEMV0 pre-activation accumulator (seeded with b0)
__device__ float g_h1[HIDD];
__device__ float g_sink[EDGE_BLOCKS * 8];  // prefetch sink (per-warp, deterministic)
__device__ int   g_idx64;         // 1 if edge_index is int64, 0 if int32

// ---------------- helpers ----------------
// Order-preserving float <-> uint32 encoding (monotone, exact round-trip).
__device__ __forceinline__ unsigned encf(float f) {
    unsigned u = __float_as_uint(f);
    return (u & 0x80000000u) ? ~u : (u | 0x80000000u);
}
__device__ __forceinline__ float decf(unsigned k) {
    unsigned u = (k & 0x80000000u) ? (k & 0x7fffffffu) : ~k;
    return __uint_as_float(u);
}
__device__ __forceinline__ float dot8(float4 a, float4 b, const float* __restrict__ w) {
    return a.x * w[0] + a.y * w[1] + a.z * w[2] + a.w * w[3]
         + b.x * w[4] + b.y * w[5] + b.z * w[6] + b.w * w[7];
}

// ---------------- kernels ----------------

// Per node: zero accumulators, encode keys from X; seed h0pre with b0.
// Thread 0 sniffs edge-index dtype: int32 data reinterpreted as int64 packs two
// random ids per word -> out-of-range values w.p. ~1 over 16 samples.
__global__ void init_kernel(const float* __restrict__ X,
                            const float* __restrict__ b0,
                            const long long* __restrict__ ei) {
    int i = blockIdx.x * blockDim.x + threadIdx.x;
    if (i == 0) {
        int ok = 1;
        #pragma unroll
        for (int k = 0; k < 16; k++) {
            long long v = ei[k];
            if (v < 0 || v >= (long long)NN) ok = 0;
        }
        g_idx64 = ok;
    }
    if (i < HIDD) g_h0pre[i] = b0[i];
    if (i >= NN) return;
    g_sc[i] = 0.0;
    // init max keys to 0: every real-data key is > 0; masked by cnt anyway
    uint4 z = make_uint4(0u, 0u, 0u, 0u);
    ((uint4*)&g_maxk[(size_t)i * FIN])[0] = z;
    ((uint4*)&g_maxk[(size_t)i * FIN])[1] = z;
    const float4* x4 = (const float4*)(X + (size_t)i * FIN);
    float4 a = x4[0], b = x4[1];
    uint4 k0 = make_uint4(encf(a.x), encf(a.y), encf(a.z), encf(a.w));
    uint4 k1 = make_uint4(encf(b.x), encf(b.y), encf(b.z), encf(b.w));
    ((uint4*)&g_key[(size_t)i * FIN])[0] = k0;
    ((uint4*)&g_key[(size_t)i * FIN])[1] = k1;
}

// Paired-lane edge kernel: lanes 2i/2i+1 share one edge; each lane loads ONE
// uint4 half of the key/max records, so the 32B node records (one 128B line
// each) cost 1 line-touch per record per edge instead of 2. Warp covers 16
// edges per step, 4 steps, all scattered loads batched. After edge work, the
// same kernel streams W0 rows [PF_ROW,HIDD) into L2 (edge phase is DRAM-idle).
__global__ void __launch_bounds__(256) edge_kernel(const void* __restrict__ eiv,
                                                   const float* __restrict__ lin_l_w,
                                                   const float* __restrict__ W0) {
    const int lane = threadIdx.x & 31;
    const int half = lane & 1;     // 0: features 0-3, 1: features 4-7
    const int sub  = lane >> 1;    // edge slot 0..15 within warp-step
    const int gw   = (blockIdx.x * 256 + threadIdx.x) >> 5;   // 0..24999
    const int base = gw * 64 + sub;

    int s[4], d[4];
    if (g_idx64) {
        const long long* EI = (const long long*)eiv;
        #pragma unroll
        for (int it = 0; it < 4; it++) {
            int e = base + it * 16;
            s[it] = (int)EI[e];
            d[it] = (int)EI[EE + e];
        }
    } else {
        const int* EI = (const int*)eiv;
        #pragma unroll
        for (int it = 0; it < 4; it++) {
            int e = base + it * 16;
            s[it] = EI[e];
            d[it] = EI[EE + e];
        }
    }

    // batch phase: 4 key halves + 4 filter halves, all independent
    uint4 k[4], c[4];
    #pragma unroll
    for (int it = 0; it < 4; it++)
        k[it] = __ldg((const uint4*)&g_key[(size_t)s[it] * FIN] + half);
    #pragma unroll
    for (int it = 0; it < 4; it++)
        c[it] = __ldg((const uint4*)&g_maxk[(size_t)d[it] * FIN] + half);
    float4 wh = __ldg((const float4*)lin_l_w + half);   // my half of lin_l_w

    // compute/RED phase
    #pragma unroll
    for (int it = 0; it < 4; it++) {
        float p4 = decf(k[it].x) * wh.x + decf(k[it].y) * wh.y
                 + decf(k[it].z) * wh.z + decf(k[it].w) * wh.w;
        p4 += __shfl_xor_sync(0xffffffffu, p4, 1);      // full dot8 on both lanes
        if (half == 0)
            atomicAdd(&g_sc[d[it]], (double)p4 + PACK24);  // mean + count, one RED
        // max path: read-filtered atomicMax on my 4 features (monotone-safe)
        unsigned* m = &g_maxk[(size_t)d[it] * FIN + half * 4];
        if (k[it].x > c[it].x) atomicMax(m + 0, k[it].x);
        if (k[it].y > c[it].y) atomicMax(m + 1, k[it].y);
        if (k[it].z > c[it].z) atomicMax(m + 2, k[it].z);
        if (k[it].w > c[it].w) atomicMax(m + 3, k[it].w);
    }

    // L2 prefetch of W0 tail rows (deterministic sink; DRAM idle otherwise)
    {
        const float4* wp = (const float4*)(W0 + (size_t)PF_ROW * NN);
        const size_t total4 = (size_t)(HIDD - PF_ROW) * NN / 4;
        const size_t stride = (size_t)EDGE_BLOCKS * 256;
        float acc = 0.0f;
        for (size_t i = blockIdx.x * 256 + threadIdx.x; i < total4; i += stride) {
            float4 v = __ldg(wp + i);
            acc += v.x + v.y + v.z + v.w;
        }
        #pragma unroll
        for (int o = 16; o; o >>= 1) acc += __shfl_down_sync(0xffffffffu, acc, o);
        if (lane == 0) g_sink[gw] = acc;
    }
}

__global__ void node_kernel(const float* __restrict__ X,
                            const float* __restrict__ lin_l_b,
                            const float* __restrict__ lin_r_w,
                            const float* __restrict__ lin_l1_w,
                            const float* __restrict__ lin_l1_b,
                            const float* __restrict__ lin_r1_w,
                            float* __restrict__ out) {
    int i = blockIdx.x * blockDim.x + threadIdx.x;
    if (i >= NN) return;
    double acc = g_sc[i];
    int cnt = __double2int_rn(acc * (1.0 / PACK24));
    float sum = (float)(acc - (double)cnt * PACK24);
    float mean = sum / fmaxf((float)cnt, 1.0f);       // agg_mean . lin_l_w
    float mx = 0.0f;
    if (cnt > 0) {
        const uint4* mk = (const uint4*)&g_maxk[(size_t)i * FIN];
        uint4 c0 = mk[0], c1 = mk[1];
        mx = decf(c0.x) * lin_l1_w[0] + decf(c0.y) * lin_l1_w[1]
           + decf(c0.z) * lin_l1_w[2] + decf(c0.w) * lin_l1_w[3]
           + decf(c1.x) * lin_l1_w[4] + decf(c1.y) * lin_l1_w[5]
           + decf(c1.z) * lin_l1_w[6] + decf(c1.w) * lin_l1_w[7];
    }
    const float4* x4 = (const float4*)(X + (size_t)i * FIN);
    float4 a = x4[0], b = x4[1];
    float hm = fmaxf(mean + lin_l_b[0]  + dot8(a, b, lin_r_w),  0.0f);
    float hx = fmaxf(mx   + lin_l1_b[0] + dot8(a, b, lin_r1_w), 0.0f);
    float v = hm + hx;
    out[i] = v;   // X_embedding slot of output
    g_x[i] = v;   // MLP input
}

// GEMV0 split (proven R4 x CH10 shape): block = (4 rows, 1 of 10 column chunks).
// x slice loaded once, reused across 4 rows. Rows below PF_ROW stream with
// __ldcs (evict-first: protect prefetched L2); rows >= PF_ROW hit L2 via __ldg.
__global__ void __launch_bounds__(256) gemv0_partial_kernel(const float* __restrict__ W0,
                                                            const float* __restrict__ x) {
    int rb    = blockIdx.x / CH;
    int chunk = blockIdx.x % CH;
    int row = rb * R4;
    const float4* x4 = (const float4*)x;
    const float4* w0 = (const float4*)(W0 + (size_t)(row + 0) * NN);
    const float4* w1 = (const float4*)(W0 + (size_t)(row + 1) * NN);
    const float4* w2 = (const float4*)(W0 + (size_t)(row + 2) * NN);
    const float4* w3 = (const float4*)(W0 + (size_t)(row + 3) * NN);
    float a0 = 0.f, a1 = 0.f, a2 = 0.f, a3 = 0.f;
    int base = chunk * C4;
    if (row >= PF_ROW) {
        for (int c = base + threadIdx.x; c < base + C4; c += 256) {
            float4 v  = x4[c];
            float4 p0 = __ldg(w0 + c);
            float4 p1 = __ldg(w1 + c);
            float4 p2 = __ldg(w2 + c);
            float4 p3 = __ldg(w3 + c);
            a0 += p0.x * v.x + p0.y * v.y + p0.z * v.z + p0.w * v.w;
            a1 += p1.x * v.x + p1.y * v.y + p1.z * v.z + p1.w * v.w;
            a2 += p2.x * v.x + p2.y * v.y + p2.z * v.z + p2.w * v.w;
            a3 += p3.x * v.x + p3.y * v.y + p3.z * v.z + p3.w * v.w;
        }
    } else {
        for (int c = base + threadIdx.x; c < base + C4; c += 256) {
            float4 v  = x4[c];
            float4 p0 = __ldcs(w0 + c);
            float4 p1 = __ldcs(w1 + c);
            float4 p2 = __ldcs(w2 + c);
            float4 p3 = __ldcs(w3 + c);
            a0 += p0.x * v.x + p0.y * v.y + p0.z * v.z + p0.w * v.w;
            a1 += p1.x * v.x + p1.y * v.y + p1.z * v.z + p1.w * v.w;
            a2 += p2.x * v.x + p2.y * v.y + p2.z * v.z + p2.w * v.w;
            a3 += p3.x * v.x + p3.y * v.y + p3.z * v.z + p3.w * v.w;
        }
    }
    __shared__ float sh[8][4];
    #pragma unroll
    for (int o = 16; o; o >>= 1) {
        a0 += __shfl_down_sync(0xffffffffu, a0, o);
        a1 += __shfl_down_sync(0xffffffffu, a1, o);
        a2 += __shfl_down_sync(0xffffffffu, a2, o);
        a3 += __shfl_down_sync(0xffffffffu, a3, o);
    }
    int lane = threadIdx.x & 31, wid = threadIdx.x >> 5;
    if (lane == 0) { sh[wid][0] = a0; sh[wid][1] = a1; sh[wid][2] = a2; sh[wid][3] = a3; }
    __syncthreads();
    if (wid == 0 && lane < 4) {
        float s = sh[0][lane] + sh[1][lane] + sh[2][lane] + sh[3][lane]
                + sh[4][lane] + sh[5][lane] + sh[6][lane] + sh[7][lane];
        atomicAdd(&g_h0pre[row + lane], s);
    }
}

// y[row] = relu(W[row,:] . act(x) + b[row]); act = relu if RELU_IN (fused from GEMV0).
template <int THREADS, int RELU_IN>
__global__ void gemv_relu_kernel(const float* __restrict__ W,
                                 const float* __restrict__ b,
                                 const float* __restrict__ x,
                                 float* __restrict__ y,
                                 int in4) {  // in_dim / 4
    int row = blockIdx.x;
    const float4* w4 = (const float4*)(W + (size_t)row * (size_t)in4 * 4);
    const float4* x4 = (const float4*)x;
    float acc = 0.0f;
    for (int c = threadIdx.x; c < in4; c += THREADS) {
        float4 w = w4[c];
        float4 v = x4[c];
        if (RELU_IN) {
            v.x = fmaxf(v.x, 0.f); v.y = fmaxf(v.y, 0.f);
            v.z = fmaxf(v.z, 0.f); v.w = fmaxf(v.w, 0.f);
        }
        acc += w.x * v.x + w.y * v.y + w.z * v.z + w.w * v.w;
    }
    __shared__ float sh[THREADS / 32];
    #pragma unroll
    for (int o = 16; o; o >>= 1) acc += __shfl_down_sync(0xffffffffu, acc, o);
    int lane = threadIdx.x & 31, wid = threadIdx.x >> 5;
    if (lane == 0) sh[wid] = acc;
    __syncthreads();
    if (wid == 0) {
        acc = (lane < THREADS / 32) ? sh[lane] : 0.0f;
        #pragma unroll
        for (int o = 16; o; o >>= 1) acc += __shfl_down_sync(0xffffffffu, acc, o);
        if (lane == 0) y[row] = fmaxf(acc + b[row], 0.0f);
    }
}

// ---------------- launch ----------------
extern "C" void kernel_launch(void* const* d_in, const int* in_sizes, int n_in,
                              void* d_out, int out_size) {
    const float* X        = (const float*)d_in[0];
    const void*  ei       = d_in[1];               // int64 or int32, detected on device
    const float* lin_l_w  = (const float*)d_in[2];
    const float* lin_l_b  = (const float*)d_in[3];
    const float* lin_r_w  = (const float*)d_in[4];
    const float* lin_l1_w = (const float*)d_in[5];
    const float* lin_l1_b = (const float*)d_in[6];
    const float* lin_r1_w = (const float*)d_in[7];
    const float* W0       = (const float*)d_in[8];
    const float* b0       = (const float*)d_in[9];
    const float* W1       = (const float*)d_in[10];
    const float* b1       = (const float*)d_in[11];
    const float* W2       = (const float*)d_in[12];
    const float* b2       = (const float*)d_in[13];
    float* out = (float*)d_out;  // [NN + RR] = embedding ++ mlp_out

    init_kernel<<<(NN + 255) / 256, 256>>>(X, b0, (const long long*)ei);
    edge_kernel<<<EDGE_BLOCKS, 256>>>(ei, lin_l_w, W0);
    node_kernel<<<(NN + 255) / 256, 256>>>(X, lin_l_b, lin_r_w,
                                           lin_l1_w, lin_l1_b, lin_r1_w, out);

    float* g_x_ptr;  float* g_h0pre_ptr;  float* g_h1_ptr;
    cudaGetSymbolAddress((void**)&g_x_ptr,     g_x);
    cudaGetSymbolAddress((void**)&g_h0pre_ptr, g_h0pre);
    cudaGetSymbolAddress((void**)&g_h1_ptr,    g_h1);

    gemv0_partial_kernel<<<(HIDD / R4) * CH, 256>>>(W0, g_x_ptr);              // 1000x50000
    gemv_relu_kernel<256, 1><<<HIDD, 256>>>(W1, b1, g_h0pre_ptr, g_h1_ptr, HIDD / 4);
    gemv_relu_kernel<256, 0><<<RR,   256>>>(W2, b2, g_h1_ptr, out + NN, HIDD / 4);
}